// round 10
// baseline (speedup 1.0000x reference)
#include <cuda_runtime.h>
#include <cuda_bf16.h>
#include <cuda_fp16.h>
#include <mma.h>

using namespace nvcuda;

#define NN 100000
#define NE 3200000
#define CH 128
#define NB ((NN + 255) / 256)   // 391 scan blocks

// Scratch (static device globals: allocation-free per harness rules)
__device__ int    g_is64;                  // 1 if edge_index is int64, 0 if int32
__device__ int    g_cnt[NN];               // in-degree (excl. self loop)
__device__ int    g_off[NN];               // CSR offsets (exclusive scan of cnt)
__device__ int    g_cur[NN];               // scatter cursors
__device__ int    g_csr[NE];               // source ids grouped by target
__device__ int    g_bsum[NB];              // per-block count sums
__device__ int    g_bpre[NB];              // exclusive prefix of block sums
__device__ float  g_dinv[NN];
__device__ float  g_xw[(size_t)NN * CH];   // X @ W fp32 (51.2 MB)
__device__ __half g_xh[(size_t)NN * CH];   // dinv * (X @ W) fp16 (25.6 MB)

// ---------------------------------------------------------------------------
// Dtype probe: int64 indices have all-zero high words; int32 pairs do not.
// ---------------------------------------------------------------------------
__global__ void k_detect(const int2* __restrict__ ei) {
    if (threadIdx.x == 0 && blockIdx.x == 0) {
        int any_hi = 0;
#pragma unroll 8
        for (int i = 0; i < 256; i++) any_hi |= ei[i].y;
        g_is64 = (any_hi == 0) ? 1 : 0;
    }
}

__device__ __forceinline__ int edge_at(const void* __restrict__ ei, long long pos) {
    if (g_is64) return (int)((const long long*)ei)[pos];
    return ((const int*)ei)[pos];
}

// ---------------------------------------------------------------------------
// CSR build: count -> 2-level parallel scan -> scatter
// ---------------------------------------------------------------------------
__global__ void k_zero_cnt() {
    int i = blockIdx.x * blockDim.x + threadIdx.x;
    if (i < NN) g_cnt[i] = 0;
}

__global__ void k_count(const void* __restrict__ ei) {
    int e = blockIdx.x * blockDim.x + threadIdx.x;
    if (e < NE) atomicAdd(&g_cnt[edge_at(ei, (long long)NE + e)], 1);
}

__global__ void __launch_bounds__(256) k_blocksum() {
    __shared__ int wsum[8];
    int i    = blockIdx.x * 256 + threadIdx.x;
    int lane = threadIdx.x & 31, wid = threadIdx.x >> 5;
    int v = (i < NN) ? g_cnt[i] : 0;
#pragma unroll
    for (int o = 16; o > 0; o >>= 1) v += __shfl_down_sync(0xFFFFFFFFu, v, o);
    if (lane == 0) wsum[wid] = v;
    __syncthreads();
    if (wid == 0) {
        int s = (lane < 8) ? wsum[lane] : 0;
#pragma unroll
        for (int o = 4; o > 0; o >>= 1) s += __shfl_down_sync(0xFFFFFFFFu, s, o);
        if (lane == 0) g_bsum[blockIdx.x] = s;
    }
}

__global__ void __launch_bounds__(512) k_scanb() {
    __shared__ int sh[512];
    int t = threadIdx.x;
    int v = (t < NB) ? g_bsum[t] : 0;
    sh[t] = v;
    __syncthreads();
    for (int o = 1; o < 512; o <<= 1) {
        int u = (t >= o) ? sh[t - o] : 0;
        __syncthreads();
        sh[t] += u;
        __syncthreads();
    }
    if (t < NB) g_bpre[t] = sh[t] - v;   // exclusive
}

__global__ void __launch_bounds__(256) k_fill() {
    __shared__ int wpre[8];
    int i    = blockIdx.x * 256 + threadIdx.x;
    int lane = threadIdx.x & 31, wid = threadIdx.x >> 5;
    int c = (i < NN) ? g_cnt[i] : 0;

    int v = c;
#pragma unroll
    for (int o = 1; o < 32; o <<= 1) {
        int u = __shfl_up_sync(0xFFFFFFFFu, v, o);
        if (lane >= o) v += u;
    }
    if (lane == 31) wpre[wid] = v;
    __syncthreads();
    if (wid == 0 && lane < 8) {
        int w = wpre[lane];
#pragma unroll
        for (int o = 1; o < 8; o <<= 1) {
            int u = __shfl_up_sync(0x000000FFu, w, o);
            if (lane >= o) w += u;
        }
        wpre[lane] = w;
    }
    __syncthreads();

    if (i < NN) {
        int excl = v - c + (wid > 0 ? wpre[wid - 1] : 0) + g_bpre[blockIdx.x];
        g_off[i]  = excl;
        g_cur[i]  = excl;
        g_dinv[i] = rsqrtf(1.0f + (float)c);
    }
}

__global__ void k_scatter(const void* __restrict__ ei) {
    int e = blockIdx.x * blockDim.x + threadIdx.x;
    if (e < NE) {
        int r = edge_at(ei, e);                     // source
        int c = edge_at(ei, (long long)NE + e);     // target
        int pos = atomicAdd(&g_cur[c], 1);
        g_csr[pos] = r;
    }
}

// ---------------------------------------------------------------------------
// Tensor-core GEMM (tf32): g_xw = X @ W, fp32 accumulate.
// Fused epilogue: block converts its own 128 rows to fp16 with dinv premult
// (g_xh = half(dinv * xw)). NOTE: no early return — __syncthreads must be
// reached by all threads.
// ---------------------------------------------------------------------------
__global__ void __launch_bounds__(256) k_gemm_tc(const float* __restrict__ X,
                                                 const float* __restrict__ W) {
    const int wid   = threadIdx.x >> 5;
    const int brow0 = blockIdx.x * 128;
    const int row0  = brow0 + wid * 16;
    const bool active = (row0 + 16) <= NN;   // full 16-row tile in range

    if (active) {
        wmma::fragment<wmma::accumulator, 16, 16, 8, float> c[8];
#pragma unroll
        for (int n = 0; n < 8; n++) wmma::fill_fragment(c[n], 0.0f);

        wmma::fragment<wmma::matrix_a, 16, 16, 8, wmma::precision::tf32, wmma::row_major> a;
        wmma::fragment<wmma::matrix_b, 16, 16, 8, wmma::precision::tf32, wmma::row_major> b;

        for (int k = 0; k < CH; k += 8) {
            wmma::load_matrix_sync(a, X + (size_t)row0 * CH + k, CH);
#pragma unroll
            for (int i = 0; i < a.num_elements; i++)
                a.x[i] = wmma::__float_to_tf32(a.x[i]);
#pragma unroll
            for (int n = 0; n < 8; n++) {
                wmma::load_matrix_sync(b, W + (size_t)k * CH + n * 16, CH);
#pragma unroll
                for (int i = 0; i < b.num_elements; i++)
                    b.x[i] = wmma::__float_to_tf32(b.x[i]);
                wmma::mma_sync(c[n], a, b, c[n]);
            }
        }

#pragma unroll
        for (int n = 0; n < 8; n++)
            wmma::store_matrix_sync(&g_xw[(size_t)row0 * CH + n * 16], c[n], CH,
                                    wmma::mem_row_major);
    }
    __syncthreads();   // gmem writes within block visible to block

    // Convert this block's rows: 128 rows x 32 float4-groups
    for (int idx = threadIdx.x; idx < 128 * 32; idx += 256) {
        int row = brow0 + (idx >> 5);
        if (row < NN) {
            int c4 = (idx & 31) * 4;
            float  s = g_dinv[row];
            float4 v = *(const float4*)&g_xw[(size_t)row * CH + c4];
            __half2 h01 = __floats2half2_rn(s * v.x, s * v.y);
            __half2 h23 = __floats2half2_rn(s * v.z, s * v.w);
            uint2 packed;
            packed.x = *(const unsigned int*)&h01;
            packed.y = *(const unsigned int*)&h23;
            *(uint2*)&g_xh[(size_t)row * CH + c4] = packed;
        }
    }
}

// ---------------------------------------------------------------------------
// Pull-mode aggregation: warp per node, HALF-WARP per edge (2 edges/iter).
//   out[c] = sc * (sum_r dinv_r*xw_r) + sc^2 * xw_c + bias,  sc = dinv[c]
// Rows gathered premultiplied fp16 (16 lanes x 16 B = 256 B row).
// ---------------------------------------------------------------------------
__global__ void __launch_bounds__(256) k_aggr(float* __restrict__ out,
                                              const float* __restrict__ bias) {
    int warp = (blockIdx.x * 256 + threadIdx.x) >> 5;
    int lane = threadIdx.x & 31;
    if (warp >= NN) return;
    const int c    = warp;
    const int off  = g_off[c];
    const int n    = g_cnt[c];
    const int half = lane >> 4;      // which edge of the pair
    const int hl   = lane & 15;      // lane within half: channels hl*8..hl*8+7
    const float sc = g_dinv[c];

    float acc[8];
#pragma unroll
    for (int k = 0; k < 8; k++) acc[k] = 0.0f;

    for (int i = 0; i < n; i += 32) {
        int m = n - i; if (m > 32) m = 32;
        int r = (lane < m) ? __ldg(&g_csr[off + i + lane]) : 0;
        for (int j = 0; j < m; j += 2) {
            int srcl = j + half;                         // per-lane source lane
            int rj = __shfl_sync(0xFFFFFFFFu, r, srcl);
            if (srcl < m) {                              // odd-tail guard
                uint4 hv = __ldg((const uint4*)&g_xh[(size_t)rj * CH + hl * 8]);
                float2 f0 = __half22float2(*(const __half2*)&hv.x);
                float2 f1 = __half22float2(*(const __half2*)&hv.y);
                float2 f2 = __half22float2(*(const __half2*)&hv.z);
                float2 f3 = __half22float2(*(const __half2*)&hv.w);
                acc[0] += f0.x; acc[1] += f0.y;
                acc[2] += f1.x; acc[3] += f1.y;
                acc[4] += f2.x; acc[5] += f2.y;
                acc[6] += f3.x; acc[7] += f3.y;
            }
        }
    }

    // combine the two half-warps (same channels live in lane and lane^16)
#pragma unroll
    for (int k = 0; k < 8; k++)
        acc[k] += __shfl_xor_sync(0xFFFFFFFFu, acc[k], 16);

    if (half == 0) {
        const float* xwc = &g_xw[(size_t)c * CH + hl * 8];
        float4 s0 = *(const float4*)xwc;
        float4 s1 = *(const float4*)(xwc + 4);
        float4 b0 = *(const float4*)&bias[hl * 8];
        float4 b1 = *(const float4*)&bias[hl * 8 + 4];
        float4 o0, o1;
        o0.x = sc * (acc[0] + sc * s0.x) + b0.x;
        o0.y = sc * (acc[1] + sc * s0.y) + b0.y;
        o0.z = sc * (acc[2] + sc * s0.z) + b0.z;
        o0.w = sc * (acc[3] + sc * s0.w) + b0.w;
        o1.x = sc * (acc[4] + sc * s1.x) + b1.x;
        o1.y = sc * (acc[5] + sc * s1.y) + b1.y;
        o1.z = sc * (acc[6] + sc * s1.z) + b1.z;
        o1.w = sc * (acc[7] + sc * s1.w) + b1.w;
        *(float4*)&out[(size_t)c * CH + hl * 8]     = o0;
        *(float4*)&out[(size_t)c * CH + hl * 8 + 4] = o1;
    }
}

// ---------------------------------------------------------------------------
extern "C" void kernel_launch(void* const* d_in, const int* in_sizes, int n_in,
                              void* d_out, int out_size) {
    const float* X    = (const float*)d_in[0];
    const void*  ei   = d_in[1];                 // [2, NE], int32 OR int64
    // d_in[2] = batch (unused by GCNConv)
    const float* W    = (const float*)d_in[3];
    const float* bias = (const float*)d_in[4];
    float*       out  = (float*)d_out;

    k_detect<<<1, 32>>>((const int2*)ei);

    // CSR build with 2-level parallel scan
    k_zero_cnt<<<NB, 256>>>();
    k_count<<<(NE + 255) / 256, 256>>>(ei);
    k_blocksum<<<NB, 256>>>();
    k_scanb<<<1, 512>>>();
    k_fill<<<NB, 256>>>();
    k_scatter<<<(NE + 255) / 256, 256>>>(ei);

    // xw = X @ W (tf32 tensor cores) + fused fp16/dinv conversion
    k_gemm_tc<<<(NN + 127) / 128, 256>>>(X, W);

    // pull-mode aggregate (warp per node, half-warp per edge)
    k_aggr<<<(NN * 32 + 255) / 256, 256>>>(out, bias);
}

// round 11
// speedup vs baseline: 1.0437x; 1.0437x over previous
#include <cuda_runtime.h>
#include <cuda_bf16.h>
#include <mma.h>

using namespace nvcuda;

#define NN 100000
#define NE 3200000
#define CH 128
#define NB ((NN + 255) / 256)   // 391 blocks over nodes

// Scratch (static device globals: allocation-free per harness rules)
__device__ int   g_is64;                  // 1 if edge_index is int64, 0 if int32
__device__ int   g_cnt[NN];               // in-degree (excl. self loop)
__device__ int   g_off[NN];               // CSR offsets (exclusive scan of cnt)
__device__ int   g_cur[NN];               // scatter cursors
__device__ int   g_csr[NE];               // source ids grouped by target
__device__ float g_dinv[NN];
__device__ float g_xw[(size_t)NN * CH];   // X @ W fp32 (51.2 MB, L2-resident)

// ---------------------------------------------------------------------------
// Launch 0: fused dtype probe + count zeroing.
// ---------------------------------------------------------------------------
__global__ void __launch_bounds__(256) k_detectzero(const int2* __restrict__ ei) {
    int i = blockIdx.x * 256 + threadIdx.x;
    if (i < NN) g_cnt[i] = 0;
    if (blockIdx.x == 0 && threadIdx.x == 0) {
        int any_hi = 0;
#pragma unroll 8
        for (int k = 0; k < 256; k++) any_hi |= ei[k].y;
        g_is64 = (any_hi == 0) ? 1 : 0;
    }
}

__device__ __forceinline__ int edge_at(const void* __restrict__ ei, long long pos) {
    if (g_is64) return (int)((const long long*)ei)[pos];
    return ((const int*)ei)[pos];
}

// ---------------------------------------------------------------------------
// Launch 1: degree histogram.
// ---------------------------------------------------------------------------
__global__ void k_count(const void* __restrict__ ei) {
    int e = blockIdx.x * blockDim.x + threadIdx.x;
    if (e < NE) atomicAdd(&g_cnt[edge_at(ei, (long long)NE + e)], 1);
}

// ---------------------------------------------------------------------------
// Launch 2: single-kernel scan. Each block computes its global prefix by
// strided-summing g_cnt[0 .. 256*bid) (L2-hit reads), then does the standard
// intra-block exclusive scan. Writes off/cur/dinv.
// ---------------------------------------------------------------------------
__global__ void __launch_bounds__(256) k_fill() {
    __shared__ int wred[8];
    __shared__ int wpre[8];
    __shared__ int s_block_prefix;
    const int tid  = threadIdx.x;
    const int lane = tid & 31, wid = tid >> 5;
    const int base = blockIdx.x * 256;

    // ---- global prefix of this block: sum g_cnt[0..base) ----
    int s = 0;
    for (int i = tid; i < base; i += 256) s += g_cnt[i];
#pragma unroll
    for (int o = 16; o > 0; o >>= 1) s += __shfl_down_sync(0xFFFFFFFFu, s, o);
    if (lane == 0) wred[wid] = s;
    __syncthreads();
    if (wid == 0) {
        int t = (lane < 8) ? wred[lane] : 0;
#pragma unroll
        for (int o = 4; o > 0; o >>= 1) t += __shfl_down_sync(0xFFFFFFFFu, t, o);
        if (lane == 0) s_block_prefix = t;
    }
    __syncthreads();

    // ---- intra-block exclusive scan of this block's 256 counts ----
    const int i = base + tid;
    int c = (i < NN) ? g_cnt[i] : 0;
    int v = c;
#pragma unroll
    for (int o = 1; o < 32; o <<= 1) {
        int u = __shfl_up_sync(0xFFFFFFFFu, v, o);
        if (lane >= o) v += u;
    }
    if (lane == 31) wpre[wid] = v;
    __syncthreads();
    if (wid == 0 && lane < 8) {
        int w = wpre[lane];
#pragma unroll
        for (int o = 1; o < 8; o <<= 1) {
            int u = __shfl_up_sync(0x000000FFu, w, o);
            if (lane >= o) w += u;
        }
        wpre[lane] = w;
    }
    __syncthreads();

    if (i < NN) {
        int excl = v - c + (wid > 0 ? wpre[wid - 1] : 0) + s_block_prefix;
        g_off[i]  = excl;
        g_cur[i]  = excl;
        g_dinv[i] = rsqrtf(1.0f + (float)c);
    }
}

// ---------------------------------------------------------------------------
// Launch 3: CSR scatter.
// ---------------------------------------------------------------------------
__global__ void k_scatter(const void* __restrict__ ei) {
    int e = blockIdx.x * blockDim.x + threadIdx.x;
    if (e < NE) {
        int r = edge_at(ei, e);                     // source
        int c = edge_at(ei, (long long)NE + e);     // target
        int pos = atomicAdd(&g_cur[c], 1);
        g_csr[pos] = r;
    }
}

// ---------------------------------------------------------------------------
// Launch 4: tensor-core GEMM (tf32): g_xw = X @ W, fp32 accumulate.
// ---------------------------------------------------------------------------
__global__ void __launch_bounds__(256) k_gemm_tc(const float* __restrict__ X,
                                                 const float* __restrict__ W) {
    const int wid  = threadIdx.x >> 5;
    const int row0 = blockIdx.x * 128 + wid * 16;
    if (row0 >= NN) return;

    wmma::fragment<wmma::accumulator, 16, 16, 8, float> c[8];
#pragma unroll
    for (int n = 0; n < 8; n++) wmma::fill_fragment(c[n], 0.0f);

    wmma::fragment<wmma::matrix_a, 16, 16, 8, wmma::precision::tf32, wmma::row_major> a;
    wmma::fragment<wmma::matrix_b, 16, 16, 8, wmma::precision::tf32, wmma::row_major> b;

    for (int k = 0; k < CH; k += 8) {
        wmma::load_matrix_sync(a, X + (size_t)row0 * CH + k, CH);
#pragma unroll
        for (int i = 0; i < a.num_elements; i++)
            a.x[i] = wmma::__float_to_tf32(a.x[i]);
#pragma unroll
        for (int n = 0; n < 8; n++) {
            wmma::load_matrix_sync(b, W + (size_t)k * CH + n * 16, CH);
#pragma unroll
            for (int i = 0; i < b.num_elements; i++)
                b.x[i] = wmma::__float_to_tf32(b.x[i]);
            wmma::mma_sync(c[n], a, b, c[n]);
        }
    }

#pragma unroll
    for (int n = 0; n < 8; n++)
        wmma::store_matrix_sync(&g_xw[(size_t)row0 * CH + n * 16], c[n], CH,
                                wmma::mem_row_major);
}

// ---------------------------------------------------------------------------
// Launch 5 (ncu target): pull-mode aggregation, warp per node, zero atomics.
//   out[c] = dinv[c] * (dinv[c]*xw[c] + sum_r dinv[r]*xw[r]) + bias
// ---------------------------------------------------------------------------
__global__ void __launch_bounds__(256) k_aggr(float* __restrict__ out,
                                              const float* __restrict__ bias) {
    int warp = (blockIdx.x * 256 + threadIdx.x) >> 5;
    int lane = threadIdx.x & 31;
    if (warp >= NN) return;
    const int c   = warp;
    const int off = g_off[c];
    const int n   = g_cnt[c];
    const float sc = g_dinv[c];

    // self-loop term
    float4 vc = *(const float4*)&g_xw[(size_t)c * CH + lane * 4];
    float4 acc = make_float4(sc * vc.x, sc * vc.y, sc * vc.z, sc * vc.w);

    for (int i = 0; i < n; i += 32) {
        int chunk = n - i; if (chunk > 32) chunk = 32;
        int   r  = 0;
        float dr = 0.0f;
        if (lane < chunk) {
            r  = __ldg(&g_csr[off + i + lane]);
            dr = __ldg(&g_dinv[r]);
        }
#pragma unroll 4
        for (int j = 0; j < chunk; j++) {
            int   rj = __shfl_sync(0xFFFFFFFFu, r, j);
            float sj = __shfl_sync(0xFFFFFFFFu, dr, j);
            float4 v = *(const float4*)&g_xw[(size_t)rj * CH + lane * 4];
            acc.x += sj * v.x; acc.y += sj * v.y;
            acc.z += sj * v.z; acc.w += sj * v.w;
        }
    }

    float4 b = *(const float4*)&bias[lane * 4];
    float4 o = make_float4(sc * acc.x + b.x, sc * acc.y + b.y,
                           sc * acc.z + b.z, sc * acc.w + b.w);
    *(float4*)&out[(size_t)c * CH + lane * 4] = o;
}

// ---------------------------------------------------------------------------
extern "C" void kernel_launch(void* const* d_in, const int* in_sizes, int n_in,
                              void* d_out, int out_size) {
    const float* X    = (const float*)d_in[0];
    const void*  ei   = d_in[1];                 // [2, NE], int32 OR int64
    // d_in[2] = batch (unused by GCNConv)
    const float* W    = (const float*)d_in[3];
    const float* bias = (const float*)d_in[4];
    float*       out  = (float*)d_out;

    k_detectzero<<<NB, 256>>>((const int2*)ei);            // launch 0
    k_count<<<(NE + 255) / 256, 256>>>(ei);                // launch 1
    k_fill<<<NB, 256>>>();                                 // launch 2
    k_scatter<<<(NE + 255) / 256, 256>>>(ei);              // launch 3
    k_gemm_tc<<<(NN + 127) / 128, 256>>>(X, W);            // launch 4
    k_aggr<<<(NN * 32 + 255) / 256, 256>>>(out, bias);     // launch 5 (ncu)
}

// round 13
// speedup vs baseline: 1.0801x; 1.0348x over previous
#include <cuda_runtime.h>
#include <cuda_bf16.h>
#include <mma.h>

using namespace nvcuda;

#define NN 100000
#define NE 3200000
#define CH 128
#define NB  ((NN + 255) / 256)   // 391 node blocks
#define SCB (NE / 4 / 256)       // 3125 scatter blocks (4 edges/thread)
#define GMB ((NN + 127) / 128)   // 782 gemm blocks

// Scratch (static device globals: allocation-free per harness rules).
// g_cnt invariant: zero at entry of every kernel_launch call (static init
// zeroes it; k_aggr re-zeroes it every call).
__device__ int   g_cnt[NN];               // in-degree (excl. self loop)
__device__ int   g_off[NN];               // CSR offsets (exclusive scan of cnt)
__device__ int   g_cur[NN];               // scatter cursors
__device__ int   g_csr[NE];               // source ids grouped by target
__device__ float g_dinv[NN];
__device__ float g_xw[(size_t)NN * CH];   // X @ W fp32 (51.2 MB, L2-resident)

// ---------------------------------------------------------------------------
// Launch 0: degree histogram, 4 edges per thread (int32 indices, proven R1).
// ---------------------------------------------------------------------------
__global__ void __launch_bounds__(256) k_count(const int4* __restrict__ cols4) {
    int t = blockIdx.x * 256 + threadIdx.x;
    if (t < NE / 4) {
        int4 v = __ldg(&cols4[t]);
        atomicAdd(&g_cnt[v.x], 1);
        atomicAdd(&g_cnt[v.y], 1);
        atomicAdd(&g_cnt[v.z], 1);
        atomicAdd(&g_cnt[v.w], 1);
    }
}

// ---------------------------------------------------------------------------
// Launch 1: single-kernel scan. Each block computes its global prefix by
// strided-summing g_cnt[0 .. 256*bid), then intra-block exclusive scan.
// Writes off/cur/dinv.
// ---------------------------------------------------------------------------
__global__ void __launch_bounds__(256) k_fill() {
    __shared__ int wred[8];
    __shared__ int wpre[8];
    __shared__ int s_block_prefix;
    const int tid  = threadIdx.x;
    const int lane = tid & 31, wid = tid >> 5;
    const int base = blockIdx.x * 256;

    int s = 0;
    for (int i = tid; i < base; i += 256) s += g_cnt[i];
#pragma unroll
    for (int o = 16; o > 0; o >>= 1) s += __shfl_down_sync(0xFFFFFFFFu, s, o);
    if (lane == 0) wred[wid] = s;
    __syncthreads();
    if (wid == 0) {
        int t = (lane < 8) ? wred[lane] : 0;
#pragma unroll
        for (int o = 4; o > 0; o >>= 1) t += __shfl_down_sync(0xFFFFFFFFu, t, o);
        if (lane == 0) s_block_prefix = t;
    }
    __syncthreads();

    const int i = base + tid;
    int c = (i < NN) ? g_cnt[i] : 0;
    int v = c;
#pragma unroll
    for (int o = 1; o < 32; o <<= 1) {
        int u = __shfl_up_sync(0xFFFFFFFFu, v, o);
        if (lane >= o) v += u;
    }
    if (lane == 31) wpre[wid] = v;
    __syncthreads();
    if (wid == 0 && lane < 8) {
        int w = wpre[lane];
#pragma unroll
        for (int o = 1; o < 8; o <<= 1) {
            int u = __shfl_up_sync(0x000000FFu, w, o);
            if (lane >= o) w += u;
        }
        wpre[lane] = w;
    }
    __syncthreads();

    if (i < NN) {
        int excl = v - c + (wid > 0 ? wpre[wid - 1] : 0) + s_block_prefix;
        g_off[i]  = excl;
        g_cur[i]  = excl;
        g_dinv[i] = rsqrtf(1.0f + (float)c);
    }
}

// ---------------------------------------------------------------------------
// Launch 2: FUSED scatter + GEMM. Blocks [0,SCB) build the CSR (4 edges per
// thread); blocks [SCB, SCB+GMB) run the tf32 wmma GEMM. Independent work,
// complementary pipes (L2 atomics vs tensor/L1). No __syncthreads anywhere.
// ---------------------------------------------------------------------------
__global__ void __launch_bounds__(256) k_scatter_gemm(const int4* __restrict__ rows4,
                                                      const int4* __restrict__ cols4,
                                                      const float* __restrict__ X,
                                                      const float* __restrict__ W) {
    if (blockIdx.x < SCB) {
        // ---- scatter ----
        int t = blockIdx.x * 256 + threadIdx.x;
        int4 r = __ldg(&rows4[t]);
        int4 c = __ldg(&cols4[t]);
        g_csr[atomicAdd(&g_cur[c.x], 1)] = r.x;
        g_csr[atomicAdd(&g_cur[c.y], 1)] = r.y;
        g_csr[atomicAdd(&g_cur[c.z], 1)] = r.z;
        g_csr[atomicAdd(&g_cur[c.w], 1)] = r.w;
    } else {
        // ---- tf32 GEMM: g_xw = X @ W ----
        const int wid  = threadIdx.x >> 5;
        const int row0 = (blockIdx.x - SCB) * 128 + wid * 16;
        if (row0 >= NN) return;

        wmma::fragment<wmma::accumulator, 16, 16, 8, float> c[8];
#pragma unroll
        for (int n = 0; n < 8; n++) wmma::fill_fragment(c[n], 0.0f);

        wmma::fragment<wmma::matrix_a, 16, 16, 8, wmma::precision::tf32, wmma::row_major> a;
        wmma::fragment<wmma::matrix_b, 16, 16, 8, wmma::precision::tf32, wmma::row_major> b;

        for (int k = 0; k < CH; k += 8) {
            wmma::load_matrix_sync(a, X + (size_t)row0 * CH + k, CH);
#pragma unroll
            for (int i = 0; i < a.num_elements; i++)
                a.x[i] = wmma::__float_to_tf32(a.x[i]);
#pragma unroll
            for (int n = 0; n < 8; n++) {
                wmma::load_matrix_sync(b, W + (size_t)k * CH + n * 16, CH);
#pragma unroll
                for (int i = 0; i < b.num_elements; i++)
                    b.x[i] = wmma::__float_to_tf32(b.x[i]);
                wmma::mma_sync(c[n], a, b, c[n]);
            }
        }

#pragma unroll
        for (int n = 0; n < 8; n++)
            wmma::store_matrix_sync(&g_xw[(size_t)row0 * CH + n * 16], c[n], CH,
                                    wmma::mem_row_major);
    }
}

// ---------------------------------------------------------------------------
// Launch 3 (ncu target): pull-mode aggregation, warp per node, zero atomics.
//   out[c] = dinv[c] * (dinv[c]*xw[c] + sum_r dinv[r]*xw[r]) + bias
// Also restores the g_cnt==0 invariant for the next call.
// ---------------------------------------------------------------------------
__global__ void __launch_bounds__(256) k_aggr(float* __restrict__ out,
                                              const float* __restrict__ bias) {
    int warp = (blockIdx.x * 256 + threadIdx.x) >> 5;
    int lane = threadIdx.x & 31;
    if (warp >= NN) return;
    const int c   = warp;
    const int off = g_off[c];
    const int n   = g_cnt[c];
    const float sc = g_dinv[c];

    // self-loop term
    float4 vc = *(const float4*)&g_xw[(size_t)c * CH + lane * 4];
    float4 acc = make_float4(sc * vc.x, sc * vc.y, sc * vc.z, sc * vc.w);

    for (int i = 0; i < n; i += 32) {
        int chunk = n - i; if (chunk > 32) chunk = 32;
        int   r  = 0;
        float dr = 0.0f;
        if (lane < chunk) {
            r  = __ldg(&g_csr[off + i + lane]);
            dr = __ldg(&g_dinv[r]);
        }
#pragma unroll 4
        for (int j = 0; j < chunk; j++) {
            int   rj = __shfl_sync(0xFFFFFFFFu, r, j);
            float sj = __shfl_sync(0xFFFFFFFFu, dr, j);
            float4 v = *(const float4*)&g_xw[(size_t)rj * CH + lane * 4];
            acc.x += sj * v.x; acc.y += sj * v.y;
            acc.z += sj * v.z; acc.w += sj * v.w;
        }
    }

    float4 b = *(const float4*)&bias[lane * 4];
    float4 o = make_float4(sc * acc.x + b.x, sc * acc.y + b.y,
                           sc * acc.z + b.z, sc * acc.w + b.w);
    *(float4*)&out[(size_t)c * CH + lane * 4] = o;

    // restore invariant for the next kernel_launch call
    if (lane == 0) g_cnt[c] = 0;
}

// ---------------------------------------------------------------------------
extern "C" void kernel_launch(void* const* d_in, const int* in_sizes, int n_in,
                              void* d_out, int out_size) {
    const float* X    = (const float*)d_in[0];
    const int*   ei   = (const int*)d_in[1];     // [2, NE] int32 (proven in R1)
    // d_in[2] = batch (unused by GCNConv)
    const float* W    = (const float*)d_in[3];
    const float* bias = (const float*)d_in[4];
    float*       out  = (float*)d_out;

    const int4* rows4 = (const int4*)ei;          // sources
    const int4* cols4 = (const int4*)(ei + NE);   // targets

    k_count<<<SCB, 256>>>(cols4);                              // launch 0
    k_fill<<<NB, 256>>>();                                     // launch 1
    k_scatter_gemm<<<SCB + GMB, 256>>>(rows4, cols4, X, W);    // launch 2
    k_aggr<<<(NN * 32 + 255) / 256, 256>>>(out, bias);         // launch 3 (ncu)
}

// round 14
// speedup vs baseline: 1.1366x; 1.0523x over previous
#include <cuda_runtime.h>
#include <cuda_bf16.h>
#include <mma.h>

using namespace nvcuda;

#define NN 100000
#define NE 3200000
#define CH 128
#define NB  ((NN + 255) / 256)   // 391 node blocks
#define SCB (NE / 4 / 256)       // 3125 edge blocks (4 edges/thread)
#define GMB ((NN + 127) / 128)   // 782 gemm blocks
#define WPAD 136                 // padded W row stride (floats): 544 B, 32B-aligned
#define GEMM_SMEM (128 * WPAD * 4)   // 69632 B

// Scratch (static device globals: allocation-free per harness rules).
// g_cnt invariant: zero at entry of every kernel_launch call (static init
// zeroes it; k_aggr re-zeroes it every call).
__device__ int   g_cnt[NN];               // in-degree (excl. self loop)
__device__ int   g_off[NN];               // CSR offsets (exclusive scan of cnt)
__device__ int   g_cur[NN];               // scatter cursors
__device__ int   g_csr[NE];               // source ids grouped by target
__device__ float g_dinv[NN];
__device__ float g_xws[(size_t)NN * CH];  // dinv[i] * (X @ W), fp32, 51.2 MB

// ---------------------------------------------------------------------------
// Launch 0: degree histogram, 4 edges per thread (int32 indices).
// ---------------------------------------------------------------------------
__global__ void __launch_bounds__(256) k_count(const int4* __restrict__ cols4) {
    int t = blockIdx.x * 256 + threadIdx.x;
    if (t < NE / 4) {
        int4 v = __ldg(&cols4[t]);
        atomicAdd(&g_cnt[v.x], 1);
        atomicAdd(&g_cnt[v.y], 1);
        atomicAdd(&g_cnt[v.z], 1);
        atomicAdd(&g_cnt[v.w], 1);
    }
}

// ---------------------------------------------------------------------------
// Launch 1: single-kernel scan (global prefix via strided re-sum) -> off/cur/dinv.
// ---------------------------------------------------------------------------
__global__ void __launch_bounds__(256) k_fill() {
    __shared__ int wred[8];
    __shared__ int wpre[8];
    __shared__ int s_block_prefix;
    const int tid  = threadIdx.x;
    const int lane = tid & 31, wid = tid >> 5;
    const int base = blockIdx.x * 256;

    int s = 0;
    for (int i = tid; i < base; i += 256) s += g_cnt[i];
#pragma unroll
    for (int o = 16; o > 0; o >>= 1) s += __shfl_down_sync(0xFFFFFFFFu, s, o);
    if (lane == 0) wred[wid] = s;
    __syncthreads();
    if (wid == 0) {
        int t = (lane < 8) ? wred[lane] : 0;
#pragma unroll
        for (int o = 4; o > 0; o >>= 1) t += __shfl_down_sync(0xFFFFFFFFu, t, o);
        if (lane == 0) s_block_prefix = t;
    }
    __syncthreads();

    const int i = base + tid;
    int c = (i < NN) ? g_cnt[i] : 0;
    int v = c;
#pragma unroll
    for (int o = 1; o < 32; o <<= 1) {
        int u = __shfl_up_sync(0xFFFFFFFFu, v, o);
        if (lane >= o) v += u;
    }
    if (lane == 31) wpre[wid] = v;
    __syncthreads();
    if (wid == 0 && lane < 8) {
        int w = wpre[lane];
#pragma unroll
        for (int o = 1; o < 8; o <<= 1) {
            int u = __shfl_up_sync(0x000000FFu, w, o);
            if (lane >= o) w += u;
        }
        wpre[lane] = w;
    }
    __syncthreads();

    if (i < NN) {
        int excl = v - c + (wid > 0 ? wpre[wid - 1] : 0) + s_block_prefix;
        g_off[i]  = excl;
        g_cur[i]  = excl;
        g_dinv[i] = rsqrtf(1.0f + (float)c);
    }
}

// ---------------------------------------------------------------------------
// Launch 2: CSR scatter, 4 edges per thread.
// ---------------------------------------------------------------------------
__global__ void __launch_bounds__(256) k_scatter(const int4* __restrict__ rows4,
                                                 const int4* __restrict__ cols4) {
    int t = blockIdx.x * 256 + threadIdx.x;
    int4 r = __ldg(&rows4[t]);
    int4 c = __ldg(&cols4[t]);
    g_csr[atomicAdd(&g_cur[c.x], 1)] = r.x;
    g_csr[atomicAdd(&g_cur[c.y], 1)] = r.y;
    g_csr[atomicAdd(&g_cur[c.z], 1)] = r.z;
    g_csr[atomicAdd(&g_cur[c.w], 1)] = r.w;
}

// ---------------------------------------------------------------------------
// Launch 3 (ncu target): tf32 GEMM with W staged in smem (8-warp reuse) and
// dinv-scaled epilogue via smem staging: g_xws = dinv[row] * (X @ W).
// No early return: 'active' keeps __syncthreads uniform.
// ---------------------------------------------------------------------------
__global__ void __launch_bounds__(256) k_gemm(const float* __restrict__ X,
                                              const float* __restrict__ W) {
    extern __shared__ float sW[];   // 128 x WPAD floats (W), reused as staging
    const int tid  = threadIdx.x;
    const int lane = tid & 31;
    const int wid  = tid >> 5;

    // stage W (coalesced read, padded write)
    for (int i = tid; i < 128 * 32; i += 256) {
        int row = i >> 5, c4 = (i & 31) * 4;
        float4 v = *(const float4*)&W[row * CH + c4];
        *(float4*)&sW[row * WPAD + c4] = v;
    }
    __syncthreads();

    const int row0 = blockIdx.x * 128 + wid * 16;
    const bool active = row0 < NN;    // NN % 16 == 0: tiles are full or absent

    wmma::fragment<wmma::accumulator, 16, 16, 8, float> c[8];
    if (active) {
#pragma unroll
        for (int n = 0; n < 8; n++) wmma::fill_fragment(c[n], 0.0f);

        wmma::fragment<wmma::matrix_a, 16, 16, 8, wmma::precision::tf32, wmma::row_major> a;
        wmma::fragment<wmma::matrix_b, 16, 16, 8, wmma::precision::tf32, wmma::row_major> b;

        for (int k = 0; k < CH; k += 8) {
            wmma::load_matrix_sync(a, X + (size_t)row0 * CH + k, CH);
#pragma unroll
            for (int i = 0; i < a.num_elements; i++)
                a.x[i] = wmma::__float_to_tf32(a.x[i]);
#pragma unroll
            for (int n = 0; n < 8; n++) {
                wmma::load_matrix_sync(b, &sW[k * WPAD + n * 16], WPAD);
#pragma unroll
                for (int i = 0; i < b.num_elements; i++)
                    b.x[i] = wmma::__float_to_tf32(b.x[i]);
                wmma::mma_sync(c[n], a, b, c[n]);
            }
        }
    }
    __syncthreads();   // everyone done reading W; smem reusable as staging

    if (active) {
        float* st = &sW[wid * 16 * WPAD];   // this warp's 16xWPAD staging slice
#pragma unroll
        for (int n = 0; n < 8; n++)
            wmma::store_matrix_sync(st + n * 16, c[n], WPAD, wmma::mem_row_major);
        __syncwarp();
        // scale rows by dinv and write out (one float4 per lane per row)
        for (int r = 0; r < 16; r++) {
            int grow = row0 + r;
            float s  = g_dinv[grow];
            float4 v = *(const float4*)&st[r * WPAD + lane * 4];
            float4 o = make_float4(s * v.x, s * v.y, s * v.z, s * v.w);
            *(float4*)&g_xws[(size_t)grow * CH + lane * 4] = o;
        }
    }
}

// ---------------------------------------------------------------------------
// Launch 4: pull-mode aggregation over pre-scaled rows, warp per node.
//   out[c] = dinv[c] * (xws[c] + sum_r xws[r]) + bias
// Inner loop: 1 SHFL + 1 LDG.128 + 4 FADD per edge. Restores g_cnt = 0.
// ---------------------------------------------------------------------------
__global__ void __launch_bounds__(256) k_aggr(float* __restrict__ out,
                                              const float* __restrict__ bias) {
    int warp = (blockIdx.x * 256 + threadIdx.x) >> 5;
    int lane = threadIdx.x & 31;
    if (warp >= NN) return;
    const int c   = warp;
    const int off = g_off[c];
    const int n   = g_cnt[c];
    const float sc = g_dinv[c];

    // self-loop term (xws already carries dinv[c])
    float4 acc = *(const float4*)&g_xws[(size_t)c * CH + lane * 4];

    for (int i = 0; i < n; i += 32) {
        int chunk = n - i; if (chunk > 32) chunk = 32;
        int r = (lane < chunk) ? __ldg(&g_csr[off + i + lane]) : 0;
#pragma unroll 4
        for (int j = 0; j < chunk; j++) {
            int rj = __shfl_sync(0xFFFFFFFFu, r, j);
            float4 v = *(const float4*)&g_xws[(size_t)rj * CH + lane * 4];
            acc.x += v.x; acc.y += v.y; acc.z += v.z; acc.w += v.w;
        }
    }

    float4 b = *(const float4*)&bias[lane * 4];
    float4 o = make_float4(sc * acc.x + b.x, sc * acc.y + b.y,
                           sc * acc.z + b.z, sc * acc.w + b.w);
    *(float4*)&out[(size_t)c * CH + lane * 4] = o;

    // restore invariant for the next kernel_launch call
    if (lane == 0) g_cnt[c] = 0;
}

// ---------------------------------------------------------------------------
extern "C" void kernel_launch(void* const* d_in, const int* in_sizes, int n_in,
                              void* d_out, int out_size) {
    const float* X    = (const float*)d_in[0];
    const int*   ei   = (const int*)d_in[1];     // [2, NE] int32
    // d_in[2] = batch (unused by GCNConv)
    const float* W    = (const float*)d_in[3];
    const float* bias = (const float*)d_in[4];
    float*       out  = (float*)d_out;

    const int4* rows4 = (const int4*)ei;          // sources
    const int4* cols4 = (const int4*)(ei + NE);   // targets

    static bool s_init = false;
    if (!s_init) {
        cudaFuncSetAttribute(k_gemm, cudaFuncAttributeMaxDynamicSharedMemorySize,
                             GEMM_SMEM);
        s_init = true;
    }

    k_count<<<SCB, 256>>>(cols4);                          // launch 0
    k_fill<<<NB, 256>>>();                                 // launch 1
    k_scatter<<<SCB, 256>>>(rows4, cols4);                 // launch 2
    k_gemm<<<GMB, 256, GEMM_SMEM>>>(X, W);                 // launch 3 (ncu)
    k_aggr<<<(NN * 32 + 255) / 256, 256>>>(out, bias);     // launch 4
}